// round 8
// baseline (speedup 1.0000x reference)
#include <cuda_runtime.h>

#define B_   2048
#define L_   64
#define N_   1024
#define E_   32
#define SE_  16
#define F_   8
#define NSH  56      // E + F + SE
#define NF   59      // NSH + 3
#define S_   20
#define T    256

// transposed conv weights: g_convT[j][n] = conv_w[n][j]  (236 KB, L2-resident)
__device__ __align__(256) float g_convT[NF * N_];
// gathered node-independent features: g_shared[b][j]  (459 KB)
__device__ __align__(256) float g_shared[B_ * NSH];

// prep: conv_w transpose (coalesced reads) + shared-feature gather
__global__ __launch_bounds__(T) void prep_kernel(
    const float* __restrict__ conv_w,     // [N, NF]
    const float* __restrict__ x_features, // [B, F]
    const int*   __restrict__ stops,      // [B, S]
    const int*   __restrict__ x_week,     // [B]
    const float* __restrict__ stop_emb,   // [N, SE]
    const float* __restrict__ week_emb)   // [NW, E]
{
    const int t = blockIdx.x * blockDim.x + threadIdx.x;

    if (t < (NF * N_) / 4) {
        float4 v = *(const float4*)(conv_w + t * 4);
        int e = t * 4;
        float vv[4] = {v.x, v.y, v.z, v.w};
        #pragma unroll
        for (int u = 0; u < 4; ++u) {
            int n = (e + u) / NF;
            int j = (e + u) - n * NF;
            g_convT[j * N_ + n] = vv[u];
        }
    }

    if (t < B_ * NSH) {
        int b = t / NSH;
        int j = t - b * NSH;
        float v;
        if (j < E_) {
            v = week_emb[x_week[b] * E_ + j];
        } else if (j < E_ + F_) {
            v = x_features[b * F_ + (j - E_)];
        } else {
            int c = j - E_ - F_;
            float s = 0.f;
            #pragma unroll
            for (int st = 0; st < S_; ++st)
                s += stop_emb[stops[b * S_ + st] * SE_ + c];
            v = s;
        }
        g_shared[t] = v;
    }
}

// fully fused: x-stream + conv dot + logits + log_softmax + mask, 2 rows/block
__global__ __launch_bounds__(T, 7) void main_kernel(
    const float* __restrict__ x,        // [B, L, N]
    const float* __restrict__ x_dist,   // [N]
    const float* __restrict__ x_markov, // [B, N]
    const int*   __restrict__ x_mask,   // [B, N]
    const float* __restrict__ conv_b,   // [N]
    const float* __restrict__ fc1_w,    // [L]
    const float* __restrict__ fc1_b,    // scalar
    float*       __restrict__ out)      // [B, N]
{
    __shared__ float s_w[L_];
    __shared__ float s_sh[2][NSH];
    __shared__ float s_red[2][8];

    const int tid  = threadIdx.x;
    const int lane = tid & 31;
    const int warp = tid >> 5;
    const int b0   = blockIdx.x * 2;
    const int n0   = tid * 4;

    if (tid < L_) s_w[tid] = fc1_w[tid];
    if (tid < 2 * NSH)
        ((float*)s_sh)[tid] = g_shared[b0 * NSH + tid];
    __syncthreads();

    // ---- phase 1: DRAM-critical x stream for both rows ----
    const float4* xb0 = (const float4*)(x + (size_t)b0 * (L_ * N_)) + tid;
    const float4* xb1 = xb0 + (L_ * N_ / 4);
    float4 a0 = make_float4(0.f, 0.f, 0.f, 0.f);
    float4 a1 = make_float4(0.f, 0.f, 0.f, 0.f);
    #pragma unroll 4
    for (int l = 0; l < L_; ++l) {
        float4 x0 = xb0[(size_t)l * (N_ / 4)];
        float4 x1 = xb1[(size_t)l * (N_ / 4)];
        float wl = s_w[l];
        a0.x = fmaf(wl, x0.x, a0.x);  a0.y = fmaf(wl, x0.y, a0.y);
        a0.z = fmaf(wl, x0.z, a0.z);  a0.w = fmaf(wl, x0.w, a0.w);
        a1.x = fmaf(wl, x1.x, a1.x);  a1.y = fmaf(wl, x1.y, a1.y);
        a1.z = fmaf(wl, x1.z, a1.z);  a1.w = fmaf(wl, x1.w, a1.w);
    }

    // ---- phase 2: conv dot (L2-hot), both rows share one convT load ----
    float d0[4] = {0.f, 0.f, 0.f, 0.f};
    float d1[4] = {0.f, 0.f, 0.f, 0.f};
    #pragma unroll 8
    for (int j = 0; j < NSH; ++j) {
        float4 wv = *(const float4*)(&g_convT[j * N_ + n0]);
        float h0 = s_sh[0][j], h1 = s_sh[1][j];
        d0[0] = fmaf(h0, wv.x, d0[0]);  d0[1] = fmaf(h0, wv.y, d0[1]);
        d0[2] = fmaf(h0, wv.z, d0[2]);  d0[3] = fmaf(h0, wv.w, d0[3]);
        d1[0] = fmaf(h1, wv.x, d1[0]);  d1[1] = fmaf(h1, wv.y, d1[1]);
        d1[2] = fmaf(h1, wv.z, d1[2]);  d1[3] = fmaf(h1, wv.w, d1[3]);
    }

    // ---- phase 3: logits ----
    float4 w56 = *(const float4*)(&g_convT[(NSH + 0) * N_ + n0]);
    float4 w57 = *(const float4*)(&g_convT[(NSH + 1) * N_ + n0]);
    float4 w58 = *(const float4*)(&g_convT[(NSH + 2) * N_ + n0]);
    float4 cb  = *(const float4*)(&conv_b[n0]);
    float4 xd  = *(const float4*)(&x_dist[n0]);
    float  fb  = *fc1_b;

    float cst0 = xd.x * w57.x + cb.x;
    float cst1 = xd.y * w57.y + cb.y;
    float cst2 = xd.z * w57.z + cb.z;
    float cst3 = xd.w * w57.w + cb.w;

    size_t base0 = (size_t)b0 * N_ + (size_t)n0;
    size_t base1 = base0 + N_;
    float4 xm0 = *(const float4*)(&x_markov[base0]);
    float4 xm1 = *(const float4*)(&x_markov[base1]);

    float p00 = d0[0] + (a0.x + fb) * w56.x + xm0.x * w58.x + cst0;
    float p01 = d0[1] + (a0.y + fb) * w56.y + xm0.y * w58.y + cst1;
    float p02 = d0[2] + (a0.z + fb) * w56.z + xm0.z * w58.z + cst2;
    float p03 = d0[3] + (a0.w + fb) * w56.w + xm0.w * w58.w + cst3;
    float p10 = d1[0] + (a1.x + fb) * w56.x + xm1.x * w58.x + cst0;
    float p11 = d1[1] + (a1.y + fb) * w56.y + xm1.y * w58.y + cst1;
    float p12 = d1[2] + (a1.z + fb) * w56.z + xm1.z * w58.z + cst2;
    float p13 = d1[3] + (a1.w + fb) * w56.w + xm1.w * w58.w + cst3;

    // ---- phase 4: dual-row log_softmax ----
    float m0 = fmaxf(fmaxf(p00, p01), fmaxf(p02, p03));
    float m1 = fmaxf(fmaxf(p10, p11), fmaxf(p12, p13));
    #pragma unroll
    for (int off = 16; off > 0; off >>= 1) {
        m0 = fmaxf(m0, __shfl_xor_sync(0xffffffffu, m0, off));
        m1 = fmaxf(m1, __shfl_xor_sync(0xffffffffu, m1, off));
    }
    if (lane == 0) { s_red[0][warp] = m0; s_red[1][warp] = m1; }
    __syncthreads();
    m0 = s_red[0][0]; m1 = s_red[1][0];
    #pragma unroll
    for (int w = 1; w < 8; ++w) {
        m0 = fmaxf(m0, s_red[0][w]);
        m1 = fmaxf(m1, s_red[1][w]);
    }
    __syncthreads();

    float s0 = __expf(p00 - m0) + __expf(p01 - m0) + __expf(p02 - m0) + __expf(p03 - m0);
    float s1 = __expf(p10 - m1) + __expf(p11 - m1) + __expf(p12 - m1) + __expf(p13 - m1);
    #pragma unroll
    for (int off = 16; off > 0; off >>= 1) {
        s0 += __shfl_xor_sync(0xffffffffu, s0, off);
        s1 += __shfl_xor_sync(0xffffffffu, s1, off);
    }
    if (lane == 0) { s_red[0][warp] = s0; s_red[1][warp] = s1; }
    __syncthreads();
    s0 = 0.f; s1 = 0.f;
    #pragma unroll
    for (int w = 0; w < 8; ++w) { s0 += s_red[0][w]; s1 += s_red[1][w]; }
    float lse0 = m0 + logf(s0);
    float lse1 = m1 + logf(s1);

    // ---- phase 5: mask + store ----
    int4 mk0 = *(const int4*)(&x_mask[base0]);
    int4 mk1 = *(const int4*)(&x_mask[base1]);
    float4 o0, o1;
    o0.x = mk0.x ? -1e8f : (p00 - lse0);
    o0.y = mk0.y ? -1e8f : (p01 - lse0);
    o0.z = mk0.z ? -1e8f : (p02 - lse0);
    o0.w = mk0.w ? -1e8f : (p03 - lse0);
    o1.x = mk1.x ? -1e8f : (p10 - lse1);
    o1.y = mk1.y ? -1e8f : (p11 - lse1);
    o1.z = mk1.z ? -1e8f : (p12 - lse1);
    o1.w = mk1.w ? -1e8f : (p13 - lse1);
    *(float4*)(&out[base0]) = o0;
    *(float4*)(&out[base1]) = o1;
}

extern "C" void kernel_launch(void* const* d_in, const int* in_sizes, int n_in,
                              void* d_out, int out_size) {
    const float* x          = (const float*)d_in[0];
    const float* x_dist     = (const float*)d_in[1];
    const float* x_features = (const float*)d_in[2];
    const float* x_markov   = (const float*)d_in[3];
    const int*   stops      = (const int*)  d_in[4];
    const int*   x_week     = (const int*)  d_in[5];
    const int*   x_mask     = (const int*)  d_in[6];
    const float* stop_emb   = (const float*)d_in[7];
    const float* week_emb   = (const float*)d_in[8];
    const float* conv_w     = (const float*)d_in[9];
    const float* conv_b     = (const float*)d_in[10];
    const float* fc1_w      = (const float*)d_in[11];
    const float* fc1_b      = (const float*)d_in[12];
    float*       out        = (float*)d_out;

    prep_kernel<<<512, T>>>(conv_w, x_features, stops, x_week, stop_emb, week_emb);
    main_kernel<<<B_ / 2, T>>>(x, x_dist, x_markov, x_mask, conv_b, fc1_w, fc1_b, out);
}

// round 9
// speedup vs baseline: 1.0777x; 1.0777x over previous
#include <cuda_runtime.h>

#define B_   2048
#define L_   64
#define N_   1024
#define E_   32
#define SE_  16
#define F_   8
#define NSH  56      // E + F + SE
#define NF   59      // NSH + 3
#define S_   20
#define T    256

// transposed conv weights: g_convT[j][n] = conv_w[n][j]  (236 KB, L2-resident)
__device__ __align__(256) float g_convT[NF * N_];
// gathered node-independent features: g_shared[b][j]  (459 KB)
__device__ __align__(256) float g_shared[B_ * NSH];

// prep: conv_w transpose (coalesced reads) + shared-feature gather
__global__ __launch_bounds__(T) void prep_kernel(
    const float* __restrict__ conv_w,     // [N, NF]
    const float* __restrict__ x_features, // [B, F]
    const int*   __restrict__ stops,      // [B, S]
    const int*   __restrict__ x_week,     // [B]
    const float* __restrict__ stop_emb,   // [N, SE]
    const float* __restrict__ week_emb)   // [NW, E]
{
    const int t = blockIdx.x * blockDim.x + threadIdx.x;

    // transpose: one scalar element per thread (coalesced reads)
    if (t < NF * N_) {
        int n = t / NF;
        int j = t - n * NF;
        g_convT[j * N_ + n] = conv_w[t];
    }

    // gather: item t = (b, j) of g_shared
    if (t < B_ * NSH) {
        int b = t / NSH;
        int j = t - b * NSH;
        float v;
        if (j < E_) {
            v = week_emb[x_week[b] * E_ + j];
        } else if (j < E_ + F_) {
            v = x_features[b * F_ + (j - E_)];
        } else {
            int c = j - E_ - F_;
            float s = 0.f;
            #pragma unroll
            for (int st = 0; st < S_; ++st)
                s += stop_emb[stops[b * S_ + st] * SE_ + c];
            v = s;
        }
        g_shared[t] = v;
    }
}

// fully fused: conv dot (stashed to smem) + sequential 2-row x-stream + softmax
__global__ __launch_bounds__(T, 7) void main_kernel(
    const float* __restrict__ x,        // [B, L, N]
    const float* __restrict__ x_dist,   // [N]
    const float* __restrict__ x_markov, // [B, N]
    const int*   __restrict__ x_mask,   // [B, N]
    const float* __restrict__ conv_b,   // [N]
    const float* __restrict__ fc1_w,    // [L]
    const float* __restrict__ fc1_b,    // scalar
    float*       __restrict__ out)      // [B, N]
{
    __shared__ float s_w[L_];
    __shared__ float s_sh[2][NSH];
    __shared__ float s_red[8];
    __shared__ float s_base[2][N_];   // row-independent part of logits (stash)
    __shared__ float s_w56[N_];       // "out"-gate weights (stash)

    const int tid  = threadIdx.x;
    const int lane = tid & 31;
    const int warp = tid >> 5;
    const int b0   = blockIdx.x * 2;
    const int n0   = tid * 4;

    if (tid < L_) s_w[tid] = fc1_w[tid];
    if (tid < 2 * NSH)
        ((float*)s_sh)[tid] = g_shared[b0 * NSH + tid];
    __syncthreads();

    // ---- phase A: conv dot for both rows (convT loaded once), stash to smem ----
    {
        float d0[4] = {0.f, 0.f, 0.f, 0.f};
        float d1[4] = {0.f, 0.f, 0.f, 0.f};
        #pragma unroll 8
        for (int j = 0; j < NSH; ++j) {
            float4 wv = *(const float4*)(&g_convT[j * N_ + n0]);
            float h0 = s_sh[0][j], h1 = s_sh[1][j];
            d0[0] = fmaf(h0, wv.x, d0[0]);  d0[1] = fmaf(h0, wv.y, d0[1]);
            d0[2] = fmaf(h0, wv.z, d0[2]);  d0[3] = fmaf(h0, wv.w, d0[3]);
            d1[0] = fmaf(h1, wv.x, d1[0]);  d1[1] = fmaf(h1, wv.y, d1[1]);
            d1[2] = fmaf(h1, wv.z, d1[2]);  d1[3] = fmaf(h1, wv.w, d1[3]);
        }

        float4 w56 = *(const float4*)(&g_convT[(NSH + 0) * N_ + n0]);
        float4 w57 = *(const float4*)(&g_convT[(NSH + 1) * N_ + n0]);
        float4 w58 = *(const float4*)(&g_convT[(NSH + 2) * N_ + n0]);
        float4 cb  = *(const float4*)(&conv_b[n0]);
        float4 xd  = *(const float4*)(&x_dist[n0]);
        float  fb  = *fc1_b;

        float c0 = xd.x * w57.x + cb.x + fb * w56.x;
        float c1 = xd.y * w57.y + cb.y + fb * w56.y;
        float c2 = xd.z * w57.z + cb.z + fb * w56.z;
        float c3 = xd.w * w57.w + cb.w + fb * w56.w;

        size_t gbase = (size_t)b0 * N_ + (size_t)n0;
        float4 xm0 = *(const float4*)(&x_markov[gbase]);
        float4 xm1 = *(const float4*)(&x_markov[gbase + N_]);

        float4 sb0, sb1;
        sb0.x = d0[0] + xm0.x * w58.x + c0;
        sb0.y = d0[1] + xm0.y * w58.y + c1;
        sb0.z = d0[2] + xm0.z * w58.z + c2;
        sb0.w = d0[3] + xm0.w * w58.w + c3;
        sb1.x = d1[0] + xm1.x * w58.x + c0;
        sb1.y = d1[1] + xm1.y * w58.y + c1;
        sb1.z = d1[2] + xm1.z * w58.z + c2;
        sb1.w = d1[3] + xm1.w * w58.w + c3;

        *(float4*)(&s_base[0][n0]) = sb0;
        *(float4*)(&s_base[1][n0]) = sb1;
        *(float4*)(&s_w56[n0])     = w56;
    }
    // no sync needed: each thread reads back only its own stash entries

    // ---- phase B: per-row stream + softmax (R5 pattern, low register pressure) ----
    #pragma unroll 1
    for (int bb = 0; bb < 2; ++bb) {
        const int b = b0 + bb;

        const float4* xb = (const float4*)(x + (size_t)b * (L_ * N_)) + tid;
        float4 acc = make_float4(0.f, 0.f, 0.f, 0.f);
        #pragma unroll 4
        for (int l = 0; l < L_; ++l) {
            float4 xv = xb[(size_t)l * (N_ / 4)];
            float wl = s_w[l];
            acc.x = fmaf(wl, xv.x, acc.x);
            acc.y = fmaf(wl, xv.y, acc.y);
            acc.z = fmaf(wl, xv.z, acc.z);
            acc.w = fmaf(wl, xv.w, acc.w);
        }

        float4 sb  = *(const float4*)(&s_base[bb][n0]);
        float4 w56 = *(const float4*)(&s_w56[n0]);

        float lg0 = sb.x + acc.x * w56.x;
        float lg1 = sb.y + acc.y * w56.y;
        float lg2 = sb.z + acc.z * w56.z;
        float lg3 = sb.w + acc.w * w56.w;

        // log_softmax over the 1024 nodes
        float m = fmaxf(fmaxf(lg0, lg1), fmaxf(lg2, lg3));
        #pragma unroll
        for (int off = 16; off > 0; off >>= 1)
            m = fmaxf(m, __shfl_xor_sync(0xffffffffu, m, off));
        if (lane == 0) s_red[warp] = m;
        __syncthreads();
        m = s_red[0];
        #pragma unroll
        for (int w = 1; w < 8; ++w) m = fmaxf(m, s_red[w]);
        __syncthreads();

        float s = __expf(lg0 - m) + __expf(lg1 - m) + __expf(lg2 - m) + __expf(lg3 - m);
        #pragma unroll
        for (int off = 16; off > 0; off >>= 1)
            s += __shfl_xor_sync(0xffffffffu, s, off);
        if (lane == 0) s_red[warp] = s;
        __syncthreads();
        s = 0.f;
        #pragma unroll
        for (int w = 0; w < 8; ++w) s += s_red[w];
        float lse = m + logf(s);

        size_t gb = (size_t)b * N_ + (size_t)n0;
        int4 mk = *(const int4*)(&x_mask[gb]);
        float4 o;
        o.x = mk.x ? -1e8f : (lg0 - lse);
        o.y = mk.y ? -1e8f : (lg1 - lse);
        o.z = mk.z ? -1e8f : (lg2 - lse);
        o.w = mk.w ? -1e8f : (lg3 - lse);
        *(float4*)(&out[gb]) = o;

        __syncthreads();  // protect s_red for next row
    }
}

extern "C" void kernel_launch(void* const* d_in, const int* in_sizes, int n_in,
                              void* d_out, int out_size) {
    const float* x          = (const float*)d_in[0];
    const float* x_dist     = (const float*)d_in[1];
    const float* x_features = (const float*)d_in[2];
    const float* x_markov   = (const float*)d_in[3];
    const int*   stops      = (const int*)  d_in[4];
    const int*   x_week     = (const int*)  d_in[5];
    const int*   x_mask     = (const int*)  d_in[6];
    const float* stop_emb   = (const float*)d_in[7];
    const float* week_emb   = (const float*)d_in[8];
    const float* conv_w     = (const float*)d_in[9];
    const float* conv_b     = (const float*)d_in[10];
    const float* fc1_w      = (const float*)d_in[11];
    const float* fc1_b      = (const float*)d_in[12];
    float*       out        = (float*)d_out;

    prep_kernel<<<1024, T>>>(conv_w, x_features, stops, x_week, stop_emb, week_emb);
    main_kernel<<<B_ / 2, T>>>(x, x_dist, x_markov, x_mask, conv_b, fc1_w, fc1_b, out);
}

// round 10
// speedup vs baseline: 1.1484x; 1.0656x over previous
#include <cuda_runtime.h>
#include <cuda_fp16.h>

#define B_   2048
#define L_   64
#define N_   1024
#define E_   32
#define SE_  16
#define F_   8
#define NSH  56      // E + F + SE
#define NF   59      // NSH + 3
#define S_   20
#define T    256
#define JP   (NSH / 2)   // 28 j-pairs

// fp16 conv weights, packed j-pairs: g_convTh[jp][n][2] = {w[2jp][n], w[2jp+1][n]}  (112 KB)
__device__ __align__(256) __half g_convTh[JP * N_ * 2];
// fp32 tail rows 56..58 of conv_w (transposed)
__device__ __align__(256) float g_tail[3 * N_];
// gathered node-independent features: g_shared[b][j]  (459 KB)
__device__ __align__(256) float g_shared[B_ * NSH];

// prep: conv_w transpose/convert + shared-feature gather
__global__ __launch_bounds__(T) void prep_kernel(
    const float* __restrict__ conv_w,     // [N, NF]
    const float* __restrict__ x_features, // [B, F]
    const int*   __restrict__ stops,      // [B, S]
    const int*   __restrict__ x_week,     // [B]
    const float* __restrict__ stop_emb,   // [N, SE]
    const float* __restrict__ week_emb)   // [NW, E]
{
    const int t = blockIdx.x * blockDim.x + threadIdx.x;

    if (t < NF * N_) {
        int n = t / NF;
        int j = t - n * NF;
        float v = conv_w[t];
        if (j < NSH)
            g_convTh[(j >> 1) * (N_ * 2) + n * 2 + (j & 1)] = __float2half(v);
        else
            g_tail[(j - NSH) * N_ + n] = v;
    }

    if (t < B_ * NSH) {
        int b = t / NSH;
        int j = t - b * NSH;
        float v;
        if (j < E_) {
            v = week_emb[x_week[b] * E_ + j];
        } else if (j < E_ + F_) {
            v = x_features[b * F_ + (j - E_)];
        } else {
            int c = j - E_ - F_;
            float s = 0.f;
            #pragma unroll
            for (int st = 0; st < S_; ++st)
                s += stop_emb[stops[b * S_ + st] * SE_ + c];
            v = s;
        }
        g_shared[t] = v;
    }
}

// fused: conv dot (fp16, stashed to smem) + 2-row x-stream + softmax, parity-staggered
__global__ __launch_bounds__(T, 7) void main_kernel(
    const float* __restrict__ x,        // [B, L, N]
    const float* __restrict__ x_dist,   // [N]
    const float* __restrict__ x_markov, // [B, N]
    const int*   __restrict__ x_mask,   // [B, N]
    const float* __restrict__ conv_b,   // [N]
    const float* __restrict__ fc1_w,    // [L]
    const float* __restrict__ fc1_b,    // scalar
    float*       __restrict__ out)      // [B, N]
{
    __shared__ float s_w[L_];
    __shared__ float s_sh[2][NSH];
    __shared__ float s_red[8];
    __shared__ float s_base[2][N_];   // row-independent part of logits
    __shared__ float s_w56[N_];       // "out"-gate weights
    __shared__ float s_acc[N_];       // acc0 stash across phase A (even blocks)

    const int tid  = threadIdx.x;
    const int lane = tid & 31;
    const int warp = tid >> 5;
    const int b0   = blockIdx.x * 2;
    const int n0   = tid * 4;
    const bool streamFirst = ((blockIdx.x & 1) == 0);

    if (tid < L_) s_w[tid] = fc1_w[tid];
    if (tid < 2 * NSH)
        ((float*)s_sh)[tid] = g_shared[b0 * NSH + tid];
    __syncthreads();

    // ---- even blocks: stream row0 FIRST (DRAM busy from t=0), stash acc ----
    if (streamFirst) {
        const float4* xb = (const float4*)(x + (size_t)b0 * (L_ * N_)) + tid;
        float4 acc = make_float4(0.f, 0.f, 0.f, 0.f);
        #pragma unroll 4
        for (int l = 0; l < L_; ++l) {
            float4 xv = xb[(size_t)l * (N_ / 4)];
            float wl = s_w[l];
            acc.x = fmaf(wl, xv.x, acc.x);
            acc.y = fmaf(wl, xv.y, acc.y);
            acc.z = fmaf(wl, xv.z, acc.z);
            acc.w = fmaf(wl, xv.w, acc.w);
        }
        *(float4*)(&s_acc[n0]) = acc;
    }

    // ---- phase A: conv dot for both rows (fp16 weights), stash to smem ----
    {
        float d00 = 0.f, d01 = 0.f, d02 = 0.f, d03 = 0.f;
        float d10 = 0.f, d11 = 0.f, d12 = 0.f, d13 = 0.f;
        #pragma unroll 4
        for (int jp = 0; jp < JP; ++jp) {
            uint4 wv = *(const uint4*)(&g_convTh[jp * (N_ * 2) + n0 * 2]);
            float2 f0 = __half22float2(*(const __half2*)&wv.x);
            float2 f1 = __half22float2(*(const __half2*)&wv.y);
            float2 f2 = __half22float2(*(const __half2*)&wv.z);
            float2 f3 = __half22float2(*(const __half2*)&wv.w);
            float h00 = s_sh[0][2 * jp], h01 = s_sh[0][2 * jp + 1];
            float h10 = s_sh[1][2 * jp], h11 = s_sh[1][2 * jp + 1];
            d00 = fmaf(h00, f0.x, fmaf(h01, f0.y, d00));
            d01 = fmaf(h00, f1.x, fmaf(h01, f1.y, d01));
            d02 = fmaf(h00, f2.x, fmaf(h01, f2.y, d02));
            d03 = fmaf(h00, f3.x, fmaf(h01, f3.y, d03));
            d10 = fmaf(h10, f0.x, fmaf(h11, f0.y, d10));
            d11 = fmaf(h10, f1.x, fmaf(h11, f1.y, d11));
            d12 = fmaf(h10, f2.x, fmaf(h11, f2.y, d12));
            d13 = fmaf(h10, f3.x, fmaf(h11, f3.y, d13));
        }

        float4 w56 = *(const float4*)(&g_tail[0 * N_ + n0]);
        float4 w57 = *(const float4*)(&g_tail[1 * N_ + n0]);
        float4 w58 = *(const float4*)(&g_tail[2 * N_ + n0]);
        float4 cb  = *(const float4*)(&conv_b[n0]);
        float4 xd  = *(const float4*)(&x_dist[n0]);
        float  fb  = *fc1_b;

        float c0 = xd.x * w57.x + cb.x + fb * w56.x;
        float c1 = xd.y * w57.y + cb.y + fb * w56.y;
        float c2 = xd.z * w57.z + cb.z + fb * w56.z;
        float c3 = xd.w * w57.w + cb.w + fb * w56.w;

        size_t gbase = (size_t)b0 * N_ + (size_t)n0;
        float4 xm0 = *(const float4*)(&x_markov[gbase]);
        float4 xm1 = *(const float4*)(&x_markov[gbase + N_]);

        float4 sb0, sb1;
        sb0.x = d00 + xm0.x * w58.x + c0;
        sb0.y = d01 + xm0.y * w58.y + c1;
        sb0.z = d02 + xm0.z * w58.z + c2;
        sb0.w = d03 + xm0.w * w58.w + c3;
        sb1.x = d10 + xm1.x * w58.x + c0;
        sb1.y = d11 + xm1.y * w58.y + c1;
        sb1.z = d12 + xm1.z * w58.z + c2;
        sb1.w = d13 + xm1.w * w58.w + c3;

        *(float4*)(&s_base[0][n0]) = sb0;
        *(float4*)(&s_base[1][n0]) = sb1;
        *(float4*)(&s_w56[n0])     = w56;
    }
    // no sync needed: each thread reads back only its own stash entries

    // ---- per-row finish (+odd blocks stream row0 here) ----
    #pragma unroll 1
    for (int bb = 0; bb < 2; ++bb) {
        const int b = b0 + bb;

        float4 acc;
        if (bb == 0 && streamFirst) {
            acc = *(const float4*)(&s_acc[n0]);
        } else {
            const float4* xb = (const float4*)(x + (size_t)b * (L_ * N_)) + tid;
            acc = make_float4(0.f, 0.f, 0.f, 0.f);
            #pragma unroll 4
            for (int l = 0; l < L_; ++l) {
                float4 xv = xb[(size_t)l * (N_ / 4)];
                float wl = s_w[l];
                acc.x = fmaf(wl, xv.x, acc.x);
                acc.y = fmaf(wl, xv.y, acc.y);
                acc.z = fmaf(wl, xv.z, acc.z);
                acc.w = fmaf(wl, xv.w, acc.w);
            }
        }

        float4 sb  = *(const float4*)(&s_base[bb][n0]);
        float4 w56 = *(const float4*)(&s_w56[n0]);

        float lg0 = sb.x + acc.x * w56.x;
        float lg1 = sb.y + acc.y * w56.y;
        float lg2 = sb.z + acc.z * w56.z;
        float lg3 = sb.w + acc.w * w56.w;

        // log_softmax over the 1024 nodes
        float m = fmaxf(fmaxf(lg0, lg1), fmaxf(lg2, lg3));
        #pragma unroll
        for (int off = 16; off > 0; off >>= 1)
            m = fmaxf(m, __shfl_xor_sync(0xffffffffu, m, off));
        if (lane == 0) s_red[warp] = m;
        __syncthreads();
        m = s_red[0];
        #pragma unroll
        for (int w = 1; w < 8; ++w) m = fmaxf(m, s_red[w]);
        __syncthreads();

        float s = __expf(lg0 - m) + __expf(lg1 - m) + __expf(lg2 - m) + __expf(lg3 - m);
        #pragma unroll
        for (int off = 16; off > 0; off >>= 1)
            s += __shfl_xor_sync(0xffffffffu, s, off);
        if (lane == 0) s_red[warp] = s;
        __syncthreads();
        s = 0.f;
        #pragma unroll
        for (int w = 0; w < 8; ++w) s += s_red[w];
        float lse = m + __logf(s);

        size_t gb = (size_t)b * N_ + (size_t)n0;
        int4 mk = *(const int4*)(&x_mask[gb]);
        float4 o;
        o.x = mk.x ? -1e8f : (lg0 - lse);
        o.y = mk.y ? -1e8f : (lg1 - lse);
        o.z = mk.z ? -1e8f : (lg2 - lse);
        o.w = mk.w ? -1e8f : (lg3 - lse);
        *(float4*)(&out[gb]) = o;

        __syncthreads();  // protect s_red for next row
    }
}

extern "C" void kernel_launch(void* const* d_in, const int* in_sizes, int n_in,
                              void* d_out, int out_size) {
    const float* x          = (const float*)d_in[0];
    const float* x_dist     = (const float*)d_in[1];
    const float* x_features = (const float*)d_in[2];
    const float* x_markov   = (const float*)d_in[3];
    const int*   stops      = (const int*)  d_in[4];
    const int*   x_week     = (const int*)  d_in[5];
    const int*   x_mask     = (const int*)  d_in[6];
    const float* stop_emb   = (const float*)d_in[7];
    const float* week_emb   = (const float*)d_in[8];
    const float* conv_w     = (const float*)d_in[9];
    const float* conv_b     = (const float*)d_in[10];
    const float* fc1_w      = (const float*)d_in[11];
    const float* fc1_b      = (const float*)d_in[12];
    float*       out        = (float*)d_out;

    prep_kernel<<<(B_ * NSH) / T, T>>>(conv_w, x_features, stops, x_week,
                                       stop_emb, week_emb);
    main_kernel<<<B_ / 2, T>>>(x, x_dist, x_markov, x_mask, conv_b, fc1_w, fc1_b, out);
}